// round 14
// baseline (speedup 1.0000x reference)
#include <cuda_runtime.h>
#include <cuda_bf16.h>
#include <cuda_fp16.h>
#include <cstdint>

#define NN 50000
#define NE 800000
#define ALPHA 0.5f

// ---------------- scratch (device globals) -----------------------------------
__device__ int    g_deg[2 * NN];    // reset to 0 by k_gather at end of each run
__device__ int    g_off[2 * NN];
__device__ int    g_cur[2 * NN];
__device__ float  g_dinv[2 * NN];
__device__ int    g_adj[2 * NE];
__device__ __half g_yh[(size_t)NN * 256];   // fp16 y, deg-scaled

__device__ __forceinline__ uint32_t smem_u32(const void* p) {
    uint32_t a;
    asm("{ .reg .u64 t; cvta.to.shared.u64 t, %1; cvt.u32.u64 %0, t; }" : "=r"(a) : "l"(p));
    return a;
}
__device__ __forceinline__ void ldsm_x4(uint32_t* r, uint32_t addr) {
    asm volatile("ldmatrix.sync.aligned.m8n8.x4.shared.b16 {%0,%1,%2,%3}, [%4];"
        : "=r"(r[0]), "=r"(r[1]), "=r"(r[2]), "=r"(r[3]) : "r"(addr));
}
__device__ __forceinline__ void ldsm_x4_t(uint32_t* r, uint32_t addr) {
    asm volatile("ldmatrix.sync.aligned.m8n8.x4.trans.shared.b16 {%0,%1,%2,%3}, [%4];"
        : "=r"(r[0]), "=r"(r[1]), "=r"(r[2]), "=r"(r[3]) : "r"(addr));
}
__device__ __forceinline__ void mma_bf16(float* c, const uint32_t* a, const uint32_t* b) {
    asm volatile(
        "mma.sync.aligned.m16n8k16.row.col.f32.bf16.bf16.f32 "
        "{%0,%1,%2,%3}, {%4,%5,%6,%7}, {%8,%9}, {%0,%1,%2,%3};"
        : "+f"(c[0]), "+f"(c[1]), "+f"(c[2]), "+f"(c[3])
        : "r"(a[0]), "r"(a[1]), "r"(a[2]), "r"(a[3]), "r"(b[0]), "r"(b[1]));
}

// ---------------- prep kernels -----------------------------------------------
__global__ void k_count(const int* __restrict__ row, const int* __restrict__ col,
                        int E, int N) {
    int t = blockIdx.x * blockDim.x + threadIdx.x;
    int e = t * 4;
    if (e + 3 < E) {
        int4 r = *(const int4*)(row + e);
        int4 c = *(const int4*)(col + e);
        atomicAdd(&g_deg[r.x], 1);
        atomicAdd(&g_deg[r.y], 1);
        atomicAdd(&g_deg[r.z], 1);
        atomicAdd(&g_deg[r.w], 1);
        atomicAdd(&g_deg[N + c.x], 1);
        atomicAdd(&g_deg[N + c.y], 1);
        atomicAdd(&g_deg[N + c.z], 1);
        atomicAdd(&g_deg[N + c.w], 1);
    } else {
        for (; e < E; e++) {
            atomicAdd(&g_deg[row[e]], 1);
            atomicAdd(&g_deg[N + col[e]], 1);
        }
    }
}

__device__ __forceinline__ int block_exscan(int val, int nwarps) {
    __shared__ int ws[16];
    int lane = threadIdx.x & 31, w = threadIdx.x >> 5;
    int inc = val;
#pragma unroll
    for (int d = 1; d < 32; d <<= 1) {
        int t = __shfl_up_sync(0xffffffffu, inc, d);
        if (lane >= d) inc += t;
    }
    if (lane == 31) ws[w] = inc;
    __syncthreads();
    if (w == 0) {
        int s = (lane < nwarps) ? ws[lane] : 0;
#pragma unroll
        for (int d = 1; d < 16; d <<= 1) {
            int t = __shfl_up_sync(0xffffffffu, s, d);
            if (lane >= d) s += t;
        }
        if (lane < nwarps) ws[lane] = s;
    }
    __syncthreads();
    int pre = (w > 0) ? ws[w - 1] : 0;
    return pre + inc - val;
}

// Single-kernel scan: block b recomputes its prefix base by reducing
// g_deg[0, b*512) directly (no inter-block communication, no spin).
__global__ void k_scan(int twoN) {
    __shared__ int red[17];
    int tid = threadIdx.x;
    int lane = tid & 31, w = tid >> 5;
    int lim = blockIdx.x * 512;

    int partial = 0;
    for (int i = tid; i < lim; i += 512) partial += g_deg[i];
#pragma unroll
    for (int d = 16; d; d >>= 1) partial += __shfl_down_sync(0xffffffffu, partial, d);
    if (lane == 0) red[w] = partial;
    __syncthreads();
    if (w == 0) {
        int x = (lane < 16) ? red[lane] : 0;
#pragma unroll
        for (int d = 8; d; d >>= 1) x += __shfl_down_sync(0xffffffffu, x, d);
        if (lane == 0) red[16] = x;
    }
    __syncthreads();
    int base = red[16];

    int i = lim + tid;
    int v = (i < twoN) ? g_deg[i] : 0;
    int ex = block_exscan(v, 16);
    if (i < twoN) {
        int o = ex + base;
        g_off[i] = o;
        g_cur[i] = o;
        g_dinv[i] = (v > 0) ? rsqrtf((float)v) : 0.0f;
    }
}

__global__ void k_fill(const int* __restrict__ row, const int* __restrict__ col,
                       int E, int N) {
    int t = blockIdx.x * blockDim.x + threadIdx.x;
    int e = t * 2;
    if (e + 1 < E) {
        int2 r = *(const int2*)(row + e);
        int2 c = *(const int2*)(col + e);
        int p0 = atomicAdd(&g_cur[r.x], 1);
        int p1 = atomicAdd(&g_cur[r.y], 1);
        int q0 = atomicAdd(&g_cur[N + c.x], 1);
        int q1 = atomicAdd(&g_cur[N + c.y], 1);
        g_adj[p0] = c.x;
        g_adj[p1] = c.y;
        g_adj[q0] = r.x;
        g_adj[q1] = r.y;
    } else if (e < E) {
        int r = row[e], c = col[e];
        int p = atomicAdd(&g_cur[r], 1);
        g_adj[p] = c;
        int q = atomicAdd(&g_cur[N + c], 1);
        g_adj[q] = r;
    }
}

// ---------------- HMMA bf16-split GEMM ---------------------------------------
#define SA_HI 0
#define SA_LO 32768
#define SB_HI 65536
#define SB_LO 131072
#define SM_TOT 196608

__global__ __launch_bounds__(256, 1) void k_gemm_mma(const float* __restrict__ X,
                                                     const float* __restrict__ Ws,
                                                     const float* __restrict__ Wd,
                                                     int M, int N) {
    extern __shared__ char sm[];
    uint32_t sb = smem_u32(sm);
    int tid = threadIdx.x, lane = tid & 31, wid = tid >> 5;
    int m0 = blockIdx.x * 128;

#pragma unroll
    for (int it = 0; it < 16; it++) {
        int i = it * 256 + tid;
        int row = i >> 5, c4 = (i & 31) << 2;
        int m = m0 + row;
        float4 v = make_float4(0.f, 0.f, 0.f, 0.f);
        if (m < M) v = *(const float4*)(X + (size_t)m * 128 + c4);
        uint32_t off = (uint32_t)row * 256u + (((uint32_t)c4 * 2u) ^ (((uint32_t)row & 7u) << 4));
        __nv_bfloat16 h[4], l2[4];
        float vv[4] = {v.x, v.y, v.z, v.w};
#pragma unroll
        for (int jj = 0; jj < 4; jj++) {
            h[jj]  = __float2bfloat16(vv[jj]);
            l2[jj] = __float2bfloat16(vv[jj] - __bfloat162float(h[jj]));
        }
        *(uint2*)(sm + SA_HI + off) = *(uint2*)h;
        *(uint2*)(sm + SA_LO + off) = *(uint2*)l2;
    }

#pragma unroll
    for (int it = 0; it < 32; it++) {
        int i = it * 256 + tid;
        int k = i >> 6, n4 = (i & 63) << 2;
        float4 v; float sc;
        if (n4 < 128) { v = *(const float4*)(Ws + (size_t)k * 128 + n4); sc = ALPHA; }
        else          { v = *(const float4*)(Wd + (size_t)k * 128 + (n4 - 128)); sc = 1.0f - ALPHA; }
        float vv[4] = {v.x * sc, v.y * sc, v.z * sc, v.w * sc};
        uint32_t off = (uint32_t)k * 512u + (((uint32_t)n4 * 2u) ^ (((uint32_t)k & 7u) << 4));
        __nv_bfloat16 h[4], l2[4];
#pragma unroll
        for (int jj = 0; jj < 4; jj++) {
            h[jj]  = __float2bfloat16(vv[jj]);
            l2[jj] = __float2bfloat16(vv[jj] - __bfloat162float(h[jj]));
        }
        *(uint2*)(sm + SB_HI + off) = *(uint2*)h;
        *(uint2*)(sm + SB_LO + off) = *(uint2*)l2;
    }
    __syncthreads();

    int wm = wid >> 2, wn = wid & 3;
    int g = lane >> 3, j = lane & 7;
    int arow_l = ((g & 1) << 3) + j;
    int akc16  = (g >> 1) << 4;
    int bkrow_l = ((g & 1) << 3) + j;
    int bnc8   = (g >> 1) << 3;

#pragma unroll
    for (int np = 0; np < 2; np++) {
        int n0w = np * 128 + wn * 32;
        float acc[4][4][4];
#pragma unroll
        for (int a = 0; a < 4; a++)
#pragma unroll
            for (int b = 0; b < 4; b++)
#pragma unroll
                for (int c = 0; c < 4; c++) acc[a][b][c] = 0.f;

#pragma unroll
        for (int ks = 0; ks < 8; ks++) {
            uint32_t ah[4][4], al[4][4];
#pragma unroll
            for (int fm = 0; fm < 4; fm++) {
                int row = wm * 64 + fm * 16 + arow_l;
                uint32_t ao = (uint32_t)row * 256u
                            + (((uint32_t)(ks * 32 + akc16)) ^ ((uint32_t)j << 4));
                ldsm_x4(ah[fm], sb + SA_HI + ao);
                ldsm_x4(al[fm], sb + SA_LO + ao);
            }
            uint32_t bh[4][2], bl[4][2];
#pragma unroll
            for (int fn2 = 0; fn2 < 2; fn2++) {
                int krow = ks * 16 + bkrow_l;
                uint32_t bo = (uint32_t)krow * 512u
                            + (((uint32_t)((n0w + fn2 * 16 + bnc8) * 2)) ^ ((uint32_t)j << 4));
                uint32_t r[4];
                ldsm_x4_t(r, sb + SB_HI + bo);
                bh[fn2 * 2][0] = r[0]; bh[fn2 * 2][1] = r[1];
                bh[fn2 * 2 + 1][0] = r[2]; bh[fn2 * 2 + 1][1] = r[3];
                ldsm_x4_t(r, sb + SB_LO + bo);
                bl[fn2 * 2][0] = r[0]; bl[fn2 * 2][1] = r[1];
                bl[fn2 * 2 + 1][0] = r[2]; bl[fn2 * 2 + 1][1] = r[3];
            }
#pragma unroll
            for (int fm = 0; fm < 4; fm++)
#pragma unroll
                for (int fn = 0; fn < 4; fn++) {
                    mma_bf16(acc[fm][fn], ah[fm], bh[fn]);
                    mma_bf16(acc[fm][fn], ah[fm], bl[fn]);
                    mma_bf16(acc[fm][fn], al[fm], bh[fn]);
                }
        }

#pragma unroll
        for (int fm = 0; fm < 4; fm++) {
            int r0 = m0 + wm * 64 + fm * 16 + (lane >> 2);
            int r1 = r0 + 8;
            float s0 = 0.f, s1 = 0.f;
            if (r0 < M) s0 = (np == 0) ? g_dinv[N + r0] : g_dinv[r0];
            if (r1 < M) s1 = (np == 0) ? g_dinv[N + r1] : g_dinv[r1];
#pragma unroll
            for (int fn = 0; fn < 4; fn++) {
                int col = n0w + fn * 8 + (lane & 3) * 2;
                if (r0 < M) {
                    *(__half2*)(g_yh + (size_t)r0 * 256 + col) =
                        __floats2half2_rn(acc[fm][fn][0] * s0, acc[fm][fn][1] * s0);
                }
                if (r1 < M) {
                    *(__half2*)(g_yh + (size_t)r1 * 256 + col) =
                        __floats2half2_rn(acc[fm][fn][2] * s1, acc[fm][fn][3] * s1);
                }
            }
        }
    }
}

// ---------------- gather: one warp per node, interleaved fwd/bwd --------------
__device__ __forceinline__ void acc_h4(float4& a, uint2 v) {
    float2 f0 = __half22float2(*(__half2*)&v.x);
    float2 f1 = __half22float2(*(__half2*)&v.y);
    a.x += f0.x; a.y += f0.y; a.z += f1.x; a.w += f1.y;
}

__global__ __launch_bounds__(256) void k_gather(const float* __restrict__ bsrc,
                                                const float* __restrict__ bdst,
                                                float* __restrict__ out, int N) {
    int wid  = (blockIdx.x * blockDim.x + threadIdx.x) >> 5;
    int lane = threadIdx.x & 31;
    if (wid >= N) return;
    int n = wid;
    const uint2* __restrict__ Y = (const uint2*)g_yh;

    float4 accf = make_float4(0.f, 0.f, 0.f, 0.f);
    float4 accb = make_float4(0.f, 0.f, 0.f, 0.f);

    int jf = g_off[n],     ef = jf + g_deg[n];
    int jb = g_off[N + n], eb = jb + g_deg[N + n];

    // interleave the two independent chains for 2x outstanding loads
    while (jf + 2 <= ef && jb + 2 <= eb) {
        int c0 = g_adj[jf], c1 = g_adj[jf + 1];
        int r0 = g_adj[jb], r1 = g_adj[jb + 1];
        uint2 v0 = Y[(size_t)c0 * 64 + lane];
        uint2 v1 = Y[(size_t)c1 * 64 + lane];
        uint2 w0 = Y[(size_t)r0 * 64 + 32 + lane];
        uint2 w1 = Y[(size_t)r1 * 64 + 32 + lane];
        acc_h4(accf, v0); acc_h4(accf, v1);
        acc_h4(accb, w0); acc_h4(accb, w1);
        jf += 2; jb += 2;
    }
    for (; jf + 4 <= ef; jf += 4) {
        int c0 = g_adj[jf], c1 = g_adj[jf + 1], c2 = g_adj[jf + 2], c3 = g_adj[jf + 3];
        uint2 v0 = Y[(size_t)c0 * 64 + lane];
        uint2 v1 = Y[(size_t)c1 * 64 + lane];
        uint2 v2 = Y[(size_t)c2 * 64 + lane];
        uint2 v3 = Y[(size_t)c3 * 64 + lane];
        acc_h4(accf, v0); acc_h4(accf, v1); acc_h4(accf, v2); acc_h4(accf, v3);
    }
    for (; jf < ef; jf++) acc_h4(accf, Y[(size_t)g_adj[jf] * 64 + lane]);
    for (; jb + 4 <= eb; jb += 4) {
        int r0 = g_adj[jb], r1 = g_adj[jb + 1], r2 = g_adj[jb + 2], r3 = g_adj[jb + 3];
        uint2 w0 = Y[(size_t)r0 * 64 + 32 + lane];
        uint2 w1 = Y[(size_t)r1 * 64 + 32 + lane];
        uint2 w2 = Y[(size_t)r2 * 64 + 32 + lane];
        uint2 w3 = Y[(size_t)r3 * 64 + 32 + lane];
        acc_h4(accb, w0); acc_h4(accb, w1); acc_h4(accb, w2); acc_h4(accb, w3);
    }
    for (; jb < eb; jb++) acc_h4(accb, Y[(size_t)g_adj[jb] * 64 + 32 + lane]);

    float df = g_dinv[n];
    float db = g_dinv[N + n];
    float4 bs = ((const float4*)bsrc)[lane];
    float4 bd = ((const float4*)bdst)[lane];
    float4 o;
    o.x = ALPHA * bs.x + (1.0f - ALPHA) * bd.x + df * accf.x + db * accb.x;
    o.y = ALPHA * bs.y + (1.0f - ALPHA) * bd.y + df * accf.y + db * accb.y;
    o.z = ALPHA * bs.z + (1.0f - ALPHA) * bd.z + df * accf.z + db * accb.z;
    o.w = ALPHA * bs.w + (1.0f - ALPHA) * bd.w + df * accf.w + db * accb.w;
    ((float4*)out)[(size_t)n * 32 + lane] = o;

    // Reset degree state for the next run (warp owns node n exclusively).
    if (lane == 0) { g_deg[n] = 0; g_deg[N + n] = 0; }
}

// ---------------- launch ------------------------------------------------------
extern "C" void kernel_launch(void* const* d_in, const int* in_sizes, int n_in,
                              void* d_out, int out_size) {
    const float* x    = (const float*)d_in[0];
    const int*   ei   = (const int*)d_in[1];
    const float* Wsrc = (const float*)d_in[2];
    const float* bsrc = (const float*)d_in[3];
    const float* Wdst = (const float*)d_in[4];
    const float* bdst = (const float*)d_in[5];
    float*       out  = (float*)d_out;

    int N = in_sizes[0] / 128;
    int E = in_sizes[1] / 2;
    if (N > NN || E > NE) return;

    int twoN = 2 * N;
    int nb   = (twoN + 511) / 512;
    int equads = (E + 3) / 4;
    int epairs = (E + 1) / 2;

    const int* row = ei;
    const int* col = ei + E;

    cudaFuncSetAttribute(k_gemm_mma, cudaFuncAttributeMaxDynamicSharedMemorySize, SM_TOT);

    k_count<<<(equads + 255) / 256, 256>>>(row, col, E, N);
    k_scan<<<nb, 512>>>(twoN);
    k_fill<<<(epairs + 255) / 256, 256>>>(row, col, E, N);
    k_gemm_mma<<<(N + 127) / 128, 256, SM_TOT>>>(x, Wsrc, Wdst, N, N);
    k_gather<<<(N * 32 + 255) / 256, 256>>>(bsrc, bdst, out, N);
}

// round 15
// speedup vs baseline: 1.0527x; 1.0527x over previous
#include <cuda_runtime.h>
#include <cuda_bf16.h>
#include <cuda_fp16.h>
#include <cstdint>

#define NN 50000
#define NE 800000
#define ALPHA 0.5f

// ---------------- scratch (device globals) -----------------------------------
__device__ int    g_deg[2 * NN];    // reset to 0 by k_gather at end of each run
__device__ int    g_off[2 * NN];
__device__ int    g_cur[2 * NN];
__device__ float  g_dinv[2 * NN];
__device__ int    g_adj[2 * NE];
__device__ __half g_yh[(size_t)NN * 256];   // fp16 y, deg-scaled
__device__ int    g_part[512];

__device__ __forceinline__ uint32_t smem_u32(const void* p) {
    uint32_t a;
    asm("{ .reg .u64 t; cvta.to.shared.u64 t, %1; cvt.u32.u64 %0, t; }" : "=r"(a) : "l"(p));
    return a;
}
__device__ __forceinline__ void ldsm_x4(uint32_t* r, uint32_t addr) {
    asm volatile("ldmatrix.sync.aligned.m8n8.x4.shared.b16 {%0,%1,%2,%3}, [%4];"
        : "=r"(r[0]), "=r"(r[1]), "=r"(r[2]), "=r"(r[3]) : "r"(addr));
}
__device__ __forceinline__ void ldsm_x4_t(uint32_t* r, uint32_t addr) {
    asm volatile("ldmatrix.sync.aligned.m8n8.x4.trans.shared.b16 {%0,%1,%2,%3}, [%4];"
        : "=r"(r[0]), "=r"(r[1]), "=r"(r[2]), "=r"(r[3]) : "r"(addr));
}
__device__ __forceinline__ void mma_bf16(float* c, const uint32_t* a, const uint32_t* b) {
    asm volatile(
        "mma.sync.aligned.m16n8k16.row.col.f32.bf16.bf16.f32 "
        "{%0,%1,%2,%3}, {%4,%5,%6,%7}, {%8,%9}, {%0,%1,%2,%3};"
        : "+f"(c[0]), "+f"(c[1]), "+f"(c[2]), "+f"(c[3])
        : "r"(a[0]), "r"(a[1]), "r"(a[2]), "r"(a[3]), "r"(b[0]), "r"(b[1]));
}

// ---------------- prep kernels (exact R10 versions) ---------------------------
__global__ void k_count(const int* __restrict__ row, const int* __restrict__ col,
                        int E, int N) {
    int t = blockIdx.x * blockDim.x + threadIdx.x;
    int e = t * 2;
    if (e + 1 < E) {
        int2 r = *(const int2*)(row + e);
        int2 c = *(const int2*)(col + e);
        atomicAdd(&g_deg[r.x], 1);
        atomicAdd(&g_deg[r.y], 1);
        atomicAdd(&g_deg[N + c.x], 1);
        atomicAdd(&g_deg[N + c.y], 1);
    } else if (e < E) {
        atomicAdd(&g_deg[row[e]], 1);
        atomicAdd(&g_deg[N + col[e]], 1);
    }
}
__device__ __forceinline__ int block_exscan(int val, int nwarps) {
    __shared__ int ws[16];
    int lane = threadIdx.x & 31, w = threadIdx.x >> 5;
    int inc = val;
#pragma unroll
    for (int d = 1; d < 32; d <<= 1) {
        int t = __shfl_up_sync(0xffffffffu, inc, d);
        if (lane >= d) inc += t;
    }
    if (lane == 31) ws[w] = inc;
    __syncthreads();
    if (w == 0) {
        int s = (lane < nwarps) ? ws[lane] : 0;
#pragma unroll
        for (int d = 1; d < 16; d <<= 1) {
            int t = __shfl_up_sync(0xffffffffu, s, d);
            if (lane >= d) s += t;
        }
        if (lane < nwarps) ws[lane] = s;
    }
    __syncthreads();
    int pre = (w > 0) ? ws[w - 1] : 0;
    return pre + inc - val;
}
__global__ void k_scan1(int twoN) {
    int i = blockIdx.x * 512 + threadIdx.x;
    int v = (i < twoN) ? g_deg[i] : 0;
    int ex = block_exscan(v, 16);
    if (i < twoN) g_off[i] = ex;
    if (threadIdx.x == 511) g_part[blockIdx.x] = ex + v;
}
__global__ void k_scan23(int twoN) {
    __shared__ int ws[17];
    int t = threadIdx.x;
    int v = (t < (int)blockIdx.x) ? g_part[t] : 0;
    int s = v;
#pragma unroll
    for (int d = 16; d; d >>= 1) s += __shfl_down_sync(0xffffffffu, s, d);
    if ((t & 31) == 0) ws[t >> 5] = s;
    __syncthreads();
    if (t < 16) {
        int x = ws[t];
#pragma unroll
        for (int d = 8; d; d >>= 1) x += __shfl_down_sync(0x0000ffffu, x, d);
        if (t == 0) ws[16] = x;
    }
    __syncthreads();
    int base = ws[16];
    int i = blockIdx.x * 512 + t;
    if (i < twoN) {
        int o = g_off[i] + base;
        g_off[i] = o;
        g_cur[i] = o;
        int d = g_deg[i];
        g_dinv[i] = (d > 0) ? rsqrtf((float)d) : 0.0f;
    }
}
__global__ void k_fill(const int* __restrict__ row, const int* __restrict__ col,
                       int E, int N) {
    int t = blockIdx.x * blockDim.x + threadIdx.x;
    int e = t * 2;
    if (e + 1 < E) {
        int2 r = *(const int2*)(row + e);
        int2 c = *(const int2*)(col + e);
        int p0 = atomicAdd(&g_cur[r.x], 1);
        int p1 = atomicAdd(&g_cur[r.y], 1);
        int q0 = atomicAdd(&g_cur[N + c.x], 1);
        int q1 = atomicAdd(&g_cur[N + c.y], 1);
        g_adj[p0] = c.x;
        g_adj[p1] = c.y;
        g_adj[q0] = r.x;
        g_adj[q1] = r.y;
    } else if (e < E) {
        int r = row[e], c = col[e];
        int p = atomicAdd(&g_cur[r], 1);
        g_adj[p] = c;
        int q = atomicAdd(&g_cur[N + c], 1);
        g_adj[q] = r;
    }
}

// ---------------- HMMA bf16-split GEMM, 512 threads ---------------------------
#define SA_HI 0
#define SA_LO 32768
#define SB_HI 65536
#define SB_LO 131072
#define SM_TOT 196608

__global__ __launch_bounds__(512, 1) void k_gemm_mma(const float* __restrict__ X,
                                                     const float* __restrict__ Ws,
                                                     const float* __restrict__ Wd,
                                                     int M, int N) {
    extern __shared__ char sm[];
    uint32_t sb = smem_u32(sm);
    int tid = threadIdx.x, lane = tid & 31, wid = tid >> 5;   // wid 0..15
    int m0 = blockIdx.x * 128;

    // --- A convert: x[m0:m0+128, 0:128] -> bf16 hi/lo (8 iters @ 512 thr) ---
#pragma unroll
    for (int it = 0; it < 8; it++) {
        int i = it * 512 + tid;
        int row = i >> 5, c4 = (i & 31) << 2;
        int m = m0 + row;
        float4 v = make_float4(0.f, 0.f, 0.f, 0.f);
        if (m < M) v = *(const float4*)(X + (size_t)m * 128 + c4);
        uint32_t off = (uint32_t)row * 256u + (((uint32_t)c4 * 2u) ^ (((uint32_t)row & 7u) << 4));
        __nv_bfloat16 h[4], l2[4];
        float vv[4] = {v.x, v.y, v.z, v.w};
#pragma unroll
        for (int jj = 0; jj < 4; jj++) {
            h[jj]  = __float2bfloat16(vv[jj]);
            l2[jj] = __float2bfloat16(vv[jj] - __bfloat162float(h[jj]));
        }
        *(uint2*)(sm + SA_HI + off) = *(uint2*)h;
        *(uint2*)(sm + SA_LO + off) = *(uint2*)l2;
    }

    // --- B convert (16 iters @ 512 thr) ---
#pragma unroll
    for (int it = 0; it < 16; it++) {
        int i = it * 512 + tid;
        int k = i >> 6, n4 = (i & 63) << 2;
        float4 v; float sc;
        if (n4 < 128) { v = *(const float4*)(Ws + (size_t)k * 128 + n4); sc = ALPHA; }
        else          { v = *(const float4*)(Wd + (size_t)k * 128 + (n4 - 128)); sc = 1.0f - ALPHA; }
        float vv[4] = {v.x * sc, v.y * sc, v.z * sc, v.w * sc};
        uint32_t off = (uint32_t)k * 512u + (((uint32_t)n4 * 2u) ^ (((uint32_t)k & 7u) << 4));
        __nv_bfloat16 h[4], l2[4];
#pragma unroll
        for (int jj = 0; jj < 4; jj++) {
            h[jj]  = __float2bfloat16(vv[jj]);
            l2[jj] = __float2bfloat16(vv[jj] - __bfloat162float(h[jj]));
        }
        *(uint2*)(sm + SB_HI + off) = *(uint2*)h;
        *(uint2*)(sm + SB_LO + off) = *(uint2*)l2;
    }
    __syncthreads();

    // warp grid 4 (M) x 4 (N); warp tile 32 rows x 32 cols per np pass
    int wm = wid >> 2, wn = wid & 3;
    int g = lane >> 3, j = lane & 7;
    int arow_l = ((g & 1) << 3) + j;
    int akc16  = (g >> 1) << 4;
    int bkrow_l = ((g & 1) << 3) + j;
    int bnc8   = (g >> 1) << 3;

#pragma unroll
    for (int np = 0; np < 2; np++) {
        int n0w = np * 128 + wn * 32;
        float acc[2][4][4];
#pragma unroll
        for (int a = 0; a < 2; a++)
#pragma unroll
            for (int b = 0; b < 4; b++)
#pragma unroll
                for (int c = 0; c < 4; c++) acc[a][b][c] = 0.f;

#pragma unroll
        for (int ks = 0; ks < 8; ks++) {
            uint32_t ah[2][4], al[2][4];
#pragma unroll
            for (int fm = 0; fm < 2; fm++) {
                int row = wm * 32 + fm * 16 + arow_l;
                uint32_t ao = (uint32_t)row * 256u
                            + (((uint32_t)(ks * 32 + akc16)) ^ ((uint32_t)j << 4));
                ldsm_x4(ah[fm], sb + SA_HI + ao);
                ldsm_x4(al[fm], sb + SA_LO + ao);
            }
            uint32_t bh[4][2], bl[4][2];
#pragma unroll
            for (int fn2 = 0; fn2 < 2; fn2++) {
                int krow = ks * 16 + bkrow_l;
                uint32_t bo = (uint32_t)krow * 512u
                            + (((uint32_t)((n0w + fn2 * 16 + bnc8) * 2)) ^ ((uint32_t)j << 4));
                uint32_t r[4];
                ldsm_x4_t(r, sb + SB_HI + bo);
                bh[fn2 * 2][0] = r[0]; bh[fn2 * 2][1] = r[1];
                bh[fn2 * 2 + 1][0] = r[2]; bh[fn2 * 2 + 1][1] = r[3];
                ldsm_x4_t(r, sb + SB_LO + bo);
                bl[fn2 * 2][0] = r[0]; bl[fn2 * 2][1] = r[1];
                bl[fn2 * 2 + 1][0] = r[2]; bl[fn2 * 2 + 1][1] = r[3];
            }
#pragma unroll
            for (int fm = 0; fm < 2; fm++)
#pragma unroll
                for (int fn = 0; fn < 4; fn++) {
                    mma_bf16(acc[fm][fn], ah[fm], bh[fn]);
                    mma_bf16(acc[fm][fn], ah[fm], bl[fn]);
                    mma_bf16(acc[fm][fn], al[fm], bh[fn]);
                }
        }

#pragma unroll
        for (int fm = 0; fm < 2; fm++) {
            int r0 = m0 + wm * 32 + fm * 16 + (lane >> 2);
            int r1 = r0 + 8;
            float s0 = 0.f, s1 = 0.f;
            if (r0 < M) s0 = (np == 0) ? g_dinv[N + r0] : g_dinv[r0];
            if (r1 < M) s1 = (np == 0) ? g_dinv[N + r1] : g_dinv[r1];
#pragma unroll
            for (int fn = 0; fn < 4; fn++) {
                int col = n0w + fn * 8 + (lane & 3) * 2;
                if (r0 < M) {
                    *(__half2*)(g_yh + (size_t)r0 * 256 + col) =
                        __floats2half2_rn(acc[fm][fn][0] * s0, acc[fm][fn][1] * s0);
                }
                if (r1 < M) {
                    *(__half2*)(g_yh + (size_t)r1 * 256 + col) =
                        __floats2half2_rn(acc[fm][fn][2] * s1, acc[fm][fn][3] * s1);
                }
            }
        }
    }
}

// ---------------- gather (exact R10 version) ----------------------------------
__device__ __forceinline__ void acc_h4(float4& a, uint2 v) {
    float2 f0 = __half22float2(*(__half2*)&v.x);
    float2 f1 = __half22float2(*(__half2*)&v.y);
    a.x += f0.x; a.y += f0.y; a.z += f1.x; a.w += f1.y;
}

__global__ __launch_bounds__(256) void k_gather(const float* __restrict__ bsrc,
                                                const float* __restrict__ bdst,
                                                float* __restrict__ out, int N) {
    int wid  = (blockIdx.x * blockDim.x + threadIdx.x) >> 5;
    int lane = threadIdx.x & 31;
    if (wid >= N) return;
    int n = wid;
    const uint2* __restrict__ Y = (const uint2*)g_yh;

    float4 accf = make_float4(0.f, 0.f, 0.f, 0.f);
    float4 accb = make_float4(0.f, 0.f, 0.f, 0.f);

    int s = g_off[n], e = s + g_deg[n];
    int j = s;
    for (; j + 4 <= e; j += 4) {
        int c0 = g_adj[j], c1 = g_adj[j + 1], c2 = g_adj[j + 2], c3 = g_adj[j + 3];
        uint2 v0 = Y[(size_t)c0 * 64 + lane];
        uint2 v1 = Y[(size_t)c1 * 64 + lane];
        uint2 v2 = Y[(size_t)c2 * 64 + lane];
        uint2 v3 = Y[(size_t)c3 * 64 + lane];
        acc_h4(accf, v0); acc_h4(accf, v1); acc_h4(accf, v2); acc_h4(accf, v3);
    }
    for (; j < e; j++) {
        acc_h4(accf, Y[(size_t)g_adj[j] * 64 + lane]);
    }

    int s2 = g_off[N + n], e2 = s2 + g_deg[N + n];
    j = s2;
    for (; j + 4 <= e2; j += 4) {
        int r0 = g_adj[j], r1 = g_adj[j + 1], r2 = g_adj[j + 2], r3 = g_adj[j + 3];
        uint2 v0 = Y[(size_t)r0 * 64 + 32 + lane];
        uint2 v1 = Y[(size_t)r1 * 64 + 32 + lane];
        uint2 v2 = Y[(size_t)r2 * 64 + 32 + lane];
        uint2 v3 = Y[(size_t)r3 * 64 + 32 + lane];
        acc_h4(accb, v0); acc_h4(accb, v1); acc_h4(accb, v2); acc_h4(accb, v3);
    }
    for (; j < e2; j++) {
        acc_h4(accb, Y[(size_t)g_adj[j] * 64 + 32 + lane]);
    }

    float df = g_dinv[n];
    float db = g_dinv[N + n];
    float4 bs = ((const float4*)bsrc)[lane];
    float4 bd = ((const float4*)bdst)[lane];
    float4 o;
    o.x = ALPHA * bs.x + (1.0f - ALPHA) * bd.x + df * accf.x + db * accb.x;
    o.y = ALPHA * bs.y + (1.0f - ALPHA) * bd.y + df * accf.y + db * accb.y;
    o.z = ALPHA * bs.z + (1.0f - ALPHA) * bd.z + df * accf.z + db * accb.z;
    o.w = ALPHA * bs.w + (1.0f - ALPHA) * bd.w + df * accf.w + db * accb.w;
    ((float4*)out)[(size_t)n * 32 + lane] = o;

    // Reset degree state for the next run (warp owns node n exclusively).
    if (lane == 0) { g_deg[n] = 0; g_deg[N + n] = 0; }
}

// ---------------- launch ------------------------------------------------------
extern "C" void kernel_launch(void* const* d_in, const int* in_sizes, int n_in,
                              void* d_out, int out_size) {
    const float* x    = (const float*)d_in[0];
    const int*   ei   = (const int*)d_in[1];
    const float* Wsrc = (const float*)d_in[2];
    const float* bsrc = (const float*)d_in[3];
    const float* Wdst = (const float*)d_in[4];
    const float* bdst = (const float*)d_in[5];
    float*       out  = (float*)d_out;

    int N = in_sizes[0] / 128;
    int E = in_sizes[1] / 2;
    if (N > NN || E > NE) return;

    int twoN = 2 * N;
    int nb   = (twoN + 511) / 512;
    int epairs = (E + 1) / 2;

    const int* row = ei;
    const int* col = ei + E;

    cudaFuncSetAttribute(k_gemm_mma, cudaFuncAttributeMaxDynamicSharedMemorySize, SM_TOT);

    k_count<<<(epairs + 255) / 256, 256>>>(row, col, E, N);
    k_scan1<<<nb, 512>>>(twoN);
    k_scan23<<<nb, 512>>>(twoN);
    k_fill<<<(epairs + 255) / 256, 256>>>(row, col, E, N);
    k_gemm_mma<<<(N + 127) / 128, 512, SM_TOT>>>(x, Wsrc, Wdst, N, N);
    k_gather<<<(N * 32 + 255) / 256, 256>>>(bsrc, bdst, out, N);
}

// round 16
// speedup vs baseline: 1.1586x; 1.1006x over previous
#include <cuda_runtime.h>
#include <cuda_bf16.h>
#include <cuda_fp16.h>
#include <cstdint>

#define NN 50000
#define NE 800000
#define ALPHA 0.5f

// ---------------- scratch (device globals) -----------------------------------
__device__ int    g_deg[2 * NN];    // reset to 0 by k_gather at end of each run
__device__ int    g_off[2 * NN];
__device__ int    g_cur[2 * NN];
__device__ float  g_dinv[2 * NN];
__device__ int    g_adj[2 * NE];
__device__ __half g_yh[(size_t)NN * 256];   // fp16 y, deg-scaled
__device__ int    g_part[512];

__device__ __forceinline__ uint32_t smem_u32(const void* p) {
    uint32_t a;
    asm("{ .reg .u64 t; cvta.to.shared.u64 t, %1; cvt.u32.u64 %0, t; }" : "=r"(a) : "l"(p));
    return a;
}
__device__ __forceinline__ void ldsm_x4(uint32_t* r, uint32_t addr) {
    asm volatile("ldmatrix.sync.aligned.m8n8.x4.shared.b16 {%0,%1,%2,%3}, [%4];"
        : "=r"(r[0]), "=r"(r[1]), "=r"(r[2]), "=r"(r[3]) : "r"(addr));
}
__device__ __forceinline__ void ldsm_x4_t(uint32_t* r, uint32_t addr) {
    asm volatile("ldmatrix.sync.aligned.m8n8.x4.trans.shared.b16 {%0,%1,%2,%3}, [%4];"
        : "=r"(r[0]), "=r"(r[1]), "=r"(r[2]), "=r"(r[3]) : "r"(addr));
}
__device__ __forceinline__ void mma_f16(float* c, const uint32_t* a, const uint32_t* b) {
    asm volatile(
        "mma.sync.aligned.m16n8k16.row.col.f32.f16.f16.f32 "
        "{%0,%1,%2,%3}, {%4,%5,%6,%7}, {%8,%9}, {%0,%1,%2,%3};"
        : "+f"(c[0]), "+f"(c[1]), "+f"(c[2]), "+f"(c[3])
        : "r"(a[0]), "r"(a[1]), "r"(a[2]), "r"(a[3]), "r"(b[0]), "r"(b[1]));
}

// ---------------- prep kernels (exact R10 versions) ---------------------------
__global__ void k_count(const int* __restrict__ row, const int* __restrict__ col,
                        int E, int N) {
    int t = blockIdx.x * blockDim.x + threadIdx.x;
    int e = t * 2;
    if (e + 1 < E) {
        int2 r = *(const int2*)(row + e);
        int2 c = *(const int2*)(col + e);
        atomicAdd(&g_deg[r.x], 1);
        atomicAdd(&g_deg[r.y], 1);
        atomicAdd(&g_deg[N + c.x], 1);
        atomicAdd(&g_deg[N + c.y], 1);
    } else if (e < E) {
        atomicAdd(&g_deg[row[e]], 1);
        atomicAdd(&g_deg[N + col[e]], 1);
    }
}
__device__ __forceinline__ int block_exscan(int val, int nwarps) {
    __shared__ int ws[16];
    int lane = threadIdx.x & 31, w = threadIdx.x >> 5;
    int inc = val;
#pragma unroll
    for (int d = 1; d < 32; d <<= 1) {
        int t = __shfl_up_sync(0xffffffffu, inc, d);
        if (lane >= d) inc += t;
    }
    if (lane == 31) ws[w] = inc;
    __syncthreads();
    if (w == 0) {
        int s = (lane < nwarps) ? ws[lane] : 0;
#pragma unroll
        for (int d = 1; d < 16; d <<= 1) {
            int t = __shfl_up_sync(0xffffffffu, s, d);
            if (lane >= d) s += t;
        }
        if (lane < nwarps) ws[lane] = s;
    }
    __syncthreads();
    int pre = (w > 0) ? ws[w - 1] : 0;
    return pre + inc - val;
}
__global__ void k_scan1(int twoN) {
    int i = blockIdx.x * 512 + threadIdx.x;
    int v = (i < twoN) ? g_deg[i] : 0;
    int ex = block_exscan(v, 16);
    if (i < twoN) g_off[i] = ex;
    if (threadIdx.x == 511) g_part[blockIdx.x] = ex + v;
}
__global__ void k_scan23(int twoN) {
    __shared__ int ws[17];
    int t = threadIdx.x;
    int v = (t < (int)blockIdx.x) ? g_part[t] : 0;
    int s = v;
#pragma unroll
    for (int d = 16; d; d >>= 1) s += __shfl_down_sync(0xffffffffu, s, d);
    if ((t & 31) == 0) ws[t >> 5] = s;
    __syncthreads();
    if (t < 16) {
        int x = ws[t];
#pragma unroll
        for (int d = 8; d; d >>= 1) x += __shfl_down_sync(0x0000ffffu, x, d);
        if (t == 0) ws[16] = x;
    }
    __syncthreads();
    int base = ws[16];
    int i = blockIdx.x * 512 + t;
    if (i < twoN) {
        int o = g_off[i] + base;
        g_off[i] = o;
        g_cur[i] = o;
        int d = g_deg[i];
        g_dinv[i] = (d > 0) ? rsqrtf((float)d) : 0.0f;
    }
}
__global__ void k_fill(const int* __restrict__ row, const int* __restrict__ col,
                       int E, int N) {
    int t = blockIdx.x * blockDim.x + threadIdx.x;
    int e = t * 2;
    if (e + 1 < E) {
        int2 r = *(const int2*)(row + e);
        int2 c = *(const int2*)(col + e);
        int p0 = atomicAdd(&g_cur[r.x], 1);
        int p1 = atomicAdd(&g_cur[r.y], 1);
        int q0 = atomicAdd(&g_cur[N + c.x], 1);
        int q1 = atomicAdd(&g_cur[N + c.y], 1);
        g_adj[p0] = c.x;
        g_adj[p1] = c.y;
        g_adj[q0] = r.x;
        g_adj[q1] = r.y;
    } else if (e < E) {
        int r = row[e], c = col[e];
        int p = atomicAdd(&g_cur[r], 1);
        g_adj[p] = c;
        int q = atomicAdd(&g_cur[N + c], 1);
        g_adj[q] = r;
    }
}

// ---------------- HMMA fp16 GEMM (single term, 96KB smem, 2 CTA/SM) ----------
#define SA 0
#define SB 32768
#define SM_TOT 98304

__global__ __launch_bounds__(256, 2) void k_gemm_mma(const float* __restrict__ X,
                                                     const float* __restrict__ Ws,
                                                     const float* __restrict__ Wd,
                                                     int M, int N) {
    extern __shared__ char sm[];
    uint32_t sb = smem_u32(sm);
    int tid = threadIdx.x, lane = tid & 31, wid = tid >> 5;
    int m0 = blockIdx.x * 128;

    // --- A convert: x[m0:m0+128, 0:128] -> fp16, swizzled (row stride 256B) ---
#pragma unroll
    for (int it = 0; it < 16; it++) {
        int i = it * 256 + tid;
        int row = i >> 5, c4 = (i & 31) << 2;
        int m = m0 + row;
        float4 v = make_float4(0.f, 0.f, 0.f, 0.f);
        if (m < M) v = *(const float4*)(X + (size_t)m * 128 + c4);
        uint32_t off = (uint32_t)row * 256u + (((uint32_t)c4 * 2u) ^ (((uint32_t)row & 7u) << 4));
        __half2 h01 = __floats2half2_rn(v.x, v.y);
        __half2 h23 = __floats2half2_rn(v.z, v.w);
        uint2 pk;
        pk.x = *(uint32_t*)&h01;
        pk.y = *(uint32_t*)&h23;
        *(uint2*)(sm + SA + off) = pk;
    }

    // --- B convert: Bsm[k][0:128]=a*Ws[k][:], [128:256]=(1-a)*Wd[k][:] -------
#pragma unroll
    for (int it = 0; it < 32; it++) {
        int i = it * 256 + tid;
        int k = i >> 6, n4 = (i & 63) << 2;
        float4 v; float sc;
        if (n4 < 128) { v = *(const float4*)(Ws + (size_t)k * 128 + n4); sc = ALPHA; }
        else          { v = *(const float4*)(Wd + (size_t)k * 128 + (n4 - 128)); sc = 1.0f - ALPHA; }
        uint32_t off = (uint32_t)k * 512u + (((uint32_t)n4 * 2u) ^ (((uint32_t)k & 7u) << 4));
        __half2 h01 = __floats2half2_rn(v.x * sc, v.y * sc);
        __half2 h23 = __floats2half2_rn(v.z * sc, v.w * sc);
        uint2 pk;
        pk.x = *(uint32_t*)&h01;
        pk.y = *(uint32_t*)&h23;
        *(uint2*)(sm + SB + off) = pk;
    }
    __syncthreads();

    int wm = wid >> 2, wn = wid & 3;     // warp grid 2 (M) x 4 (N)
    int g = lane >> 3, j = lane & 7;
    int arow_l = ((g & 1) << 3) + j;
    int akc16  = (g >> 1) << 4;
    int bkrow_l = ((g & 1) << 3) + j;
    int bnc8   = (g >> 1) << 3;

#pragma unroll
    for (int np = 0; np < 2; np++) {
        int n0w = np * 128 + wn * 32;
        float acc[4][4][4];
#pragma unroll
        for (int a = 0; a < 4; a++)
#pragma unroll
            for (int b = 0; b < 4; b++)
#pragma unroll
                for (int c = 0; c < 4; c++) acc[a][b][c] = 0.f;

#pragma unroll
        for (int ks = 0; ks < 8; ks++) {
            uint32_t ah[4][4];
#pragma unroll
            for (int fm = 0; fm < 4; fm++) {
                int row = wm * 64 + fm * 16 + arow_l;
                uint32_t ao = (uint32_t)row * 256u
                            + (((uint32_t)(ks * 32 + akc16)) ^ ((uint32_t)j << 4));
                ldsm_x4(ah[fm], sb + SA + ao);
            }
            uint32_t bh[4][2];
#pragma unroll
            for (int fn2 = 0; fn2 < 2; fn2++) {
                int krow = ks * 16 + bkrow_l;
                uint32_t bo = (uint32_t)krow * 512u
                            + (((uint32_t)((n0w + fn2 * 16 + bnc8) * 2)) ^ ((uint32_t)j << 4));
                uint32_t r[4];
                ldsm_x4_t(r, sb + SB + bo);
                bh[fn2 * 2][0] = r[0]; bh[fn2 * 2][1] = r[1];
                bh[fn2 * 2 + 1][0] = r[2]; bh[fn2 * 2 + 1][1] = r[3];
            }
#pragma unroll
            for (int fm = 0; fm < 4; fm++)
#pragma unroll
                for (int fn = 0; fn < 4; fn++)
                    mma_f16(acc[fm][fn], ah[fm], bh[fn]);
        }

#pragma unroll
        for (int fm = 0; fm < 4; fm++) {
            int r0 = m0 + wm * 64 + fm * 16 + (lane >> 2);
            int r1 = r0 + 8;
            float s0 = 0.f, s1 = 0.f;
            if (r0 < M) s0 = (np == 0) ? g_dinv[N + r0] : g_dinv[r0];
            if (r1 < M) s1 = (np == 0) ? g_dinv[N + r1] : g_dinv[r1];
#pragma unroll
            for (int fn = 0; fn < 4; fn++) {
                int col = n0w + fn * 8 + (lane & 3) * 2;
                if (r0 < M) {
                    *(__half2*)(g_yh + (size_t)r0 * 256 + col) =
                        __floats2half2_rn(acc[fm][fn][0] * s0, acc[fm][fn][1] * s0);
                }
                if (r1 < M) {
                    *(__half2*)(g_yh + (size_t)r1 * 256 + col) =
                        __floats2half2_rn(acc[fm][fn][2] * s1, acc[fm][fn][3] * s1);
                }
            }
        }
    }
}

// ---------------- gather (exact R10 version) ----------------------------------
__device__ __forceinline__ void acc_h4(float4& a, uint2 v) {
    float2 f0 = __half22float2(*(__half2*)&v.x);
    float2 f1 = __half22float2(*(__half2*)&v.y);
    a.x += f0.x; a.y += f0.y; a.z += f1.x; a.w += f1.y;
}

__global__ __launch_bounds__(256) void k_gather(const float* __restrict__ bsrc,
                                                const float* __restrict__ bdst,
                                                float* __restrict__ out, int N) {
    int wid  = (blockIdx.x * blockDim.x + threadIdx.x) >> 5;
    int lane = threadIdx.x & 31;
    if (wid >= N) return;
    int n = wid;
    const uint2* __restrict__ Y = (const uint2*)g_yh;

    float4 accf = make_float4(0.f, 0.f, 0.f, 0.f);
    float4 accb = make_float4(0.f, 0.f, 0.f, 0.f);

    int s = g_off[n], e = s + g_deg[n];
    int j = s;
    for (; j + 4 <= e; j += 4) {
        int c0 = g_adj[j], c1 = g_adj[j + 1], c2 = g_adj[j + 2], c3 = g_adj[j + 3];
        uint2 v0 = Y[(size_t)c0 * 64 + lane];
        uint2 v1 = Y[(size_t)c1 * 64 + lane];
        uint2 v2 = Y[(size_t)c2 * 64 + lane];
        uint2 v3 = Y[(size_t)c3 * 64 + lane];
        acc_h4(accf, v0); acc_h4(accf, v1); acc_h4(accf, v2); acc_h4(accf, v3);
    }
    for (; j < e; j++) {
        acc_h4(accf, Y[(size_t)g_adj[j] * 64 + lane]);
    }

    int s2 = g_off[N + n], e2 = s2 + g_deg[N + n];
    j = s2;
    for (; j + 4 <= e2; j += 4) {
        int r0 = g_adj[j], r1 = g_adj[j + 1], r2 = g_adj[j + 2], r3 = g_adj[j + 3];
        uint2 v0 = Y[(size_t)r0 * 64 + 32 + lane];
        uint2 v1 = Y[(size_t)r1 * 64 + 32 + lane];
        uint2 v2 = Y[(size_t)r2 * 64 + 32 + lane];
        uint2 v3 = Y[(size_t)r3 * 64 + 32 + lane];
        acc_h4(accb, v0); acc_h4(accb, v1); acc_h4(accb, v2); acc_h4(accb, v3);
    }
    for (; j < e2; j++) {
        acc_h4(accb, Y[(size_t)g_adj[j] * 64 + 32 + lane]);
    }

    float df = g_dinv[n];
    float db = g_dinv[N + n];
    float4 bs = ((const float4*)bsrc)[lane];
    float4 bd = ((const float4*)bdst)[lane];
    float4 o;
    o.x = ALPHA * bs.x + (1.0f - ALPHA) * bd.x + df * accf.x + db * accb.x;
    o.y = ALPHA * bs.y + (1.0f - ALPHA) * bd.y + df * accf.y + db * accb.y;
    o.z = ALPHA * bs.z + (1.0f - ALPHA) * bd.z + df * accf.z + db * accb.z;
    o.w = ALPHA * bs.w + (1.0f - ALPHA) * bd.w + df * accf.w + db * accb.w;
    ((float4*)out)[(size_t)n * 32 + lane] = o;

    // Reset degree state for the next run (warp owns node n exclusively).
    if (lane == 0) { g_deg[n] = 0; g_deg[N + n] = 0; }
}

// ---------------- launch ------------------------------------------------------
extern "C" void kernel_launch(void* const* d_in, const int* in_sizes, int n_in,
                              void* d_out, int out_size) {
    const float* x    = (const float*)d_in[0];
    const int*   ei   = (const int*)d_in[1];
    const float* Wsrc = (const float*)d_in[2];
    const float* bsrc = (const float*)d_in[3];
    const float* Wdst = (const float*)d_in[4];
    const float* bdst = (const float*)d_in[5];
    float*       out  = (float*)d_out;

    int N = in_sizes[0] / 128;
    int E = in_sizes[1] / 2;
    if (N > NN || E > NE) return;

    int twoN = 2 * N;
    int nb   = (twoN + 511) / 512;
    int epairs = (E + 1) / 2;

    const int* row = ei;
    const int* col = ei + E;

    cudaFuncSetAttribute(k_gemm_mma, cudaFuncAttributeMaxDynamicSharedMemorySize, SM_TOT);

    k_count<<<(epairs + 255) / 256, 256>>>(row, col, E, N);
    k_scan1<<<nb, 512>>>(twoN);
    k_scan23<<<nb, 512>>>(twoN);
    k_fill<<<(epairs + 255) / 256, 256>>>(row, col, E, N);
    k_gemm_mma<<<(N + 127) / 128, 256, SM_TOT>>>(x, Wsrc, Wdst, N, N);
    k_gather<<<(N * 32 + 255) / 256, 256>>>(bsrc, bdst, out, N);
}